// round 7
// baseline (speedup 1.0000x reference)
#include <cuda_runtime.h>
#include <cstdint>

// Problem constants (match reference)
#define NUM_MOVABLE 10000000
#define NUM_PHYS    11000000
#define BXD 32
#define BYD 32
#define NBINS (BXD * BYD)

#define HIST_BLOCKS 592   // 4 CTAs/SM on 148 SMs
#define HIST_THREADS 256

// Global scratch accumulators (no cudaMalloc allowed).
// Zero-initialized at module load; the finishing block resets them to zero
// after consuming them, so the "all zero on kernel entry" invariant holds
// across every graph replay. Fixed-point units of 1/512.
// gA = S(low32) | Sx(high32); gB = Sy | Sxy.
__device__ unsigned long long gA[NBINS];
__device__ unsigned long long gB[NBINS];
__device__ unsigned int g_ctr;   // wraps back to 0 every full grid

// Moments at source bin (iy,ix):  S += a, Sx += a*dx, Sy += a*dy, Sxy += a*dx*dy.
// density(j,i) = (S-Sx-Sy+Sxy)[j,i] + (Sx-Sxy)[j,i-1] + (Sy-Sxy)[j-1,i] + Sxy[j-1,i-1].
__global__ void __launch_bounds__(HIST_THREADS)
fused_kernel(const float4* __restrict__ x4,
             const float4* __restrict__ y4,
             const int4*   __restrict__ m4,    // mask is int32 per element
             const float4* __restrict__ sx4,
             const float4* __restrict__ sy4,
             float* __restrict__ out) {
    __shared__ unsigned long long sh[NBINS];   // 4x16-bit fields: S,adx,ady,adxy (1/512 units)
    for (int i = threadIdx.x; i < NBINS; i += HIST_THREADS) sh[i] = 0ull;
    __syncthreads();

    const float CLMP  = 30.9999990463f;        // float(31 - 1e-6)
    const float MAGIC = 8388608.0f;            // 2^23, RNE-to-integer trick

    const int n4 = NUM_MOVABLE / 4;            // 2,500,000 exact
    for (int i = blockIdx.x * HIST_THREADS + threadIdx.x; i < n4;
         i += HIST_BLOCKS * HIST_THREADS) {
        float4 x  = __ldg(x4  + i);
        float4 y  = __ldg(y4  + i);
        float4 sx = __ldg(sx4 + i);
        float4 sy = __ldg(sy4 + i);
        int4   m  = __ldg(m4  + i);

        #pragma unroll
        for (int k = 0; k < 4; k++) {
            float xv  = (k == 0) ? x.x  : (k == 1) ? x.y  : (k == 2) ? x.z  : x.w;
            float yv  = (k == 0) ? y.x  : (k == 1) ? y.y  : (k == 2) ? y.z  : y.w;
            float sxv = (k == 0) ? sx.x : (k == 1) ? sx.y : (k == 2) ? sx.z : sx.w;
            float syv = (k == 0) ? sy.x : (k == 1) ? sy.y : (k == 2) ? sy.z : sy.w;
            int   mv  = (k == 0) ? m.x  : (k == 1) ? m.y  : (k == 2) ? m.z  : m.w;

            float fx = fminf(fmaxf(xv * 32.0f, 0.0f), CLMP);
            float fy = fminf(fmaxf(yv * 32.0f, 0.0f), CLMP);
            unsigned qx = __float_as_uint(fmaf(fx, 65536.0f, MAGIC)) & 0x3FFFFF;
            unsigned qy = __float_as_uint(fmaf(fy, 65536.0f, MAGIC)) & 0x3FFFFF;

            float a = fminf(sxv * 32.0f, 1.0f) * fminf(syv * 32.0f, 1.0f);
            if (mv == 0) a = 0.0f;
            unsigned a512 = __float_as_uint(fmaf(a, 512.0f, MAGIC)) & 0xFFFF;

            unsigned dxq = qx & 0xFFFFu;       // dx in 2^-16 units
            unsigned dyq = qy & 0xFFFFu;
            unsigned ix  = qx >> 16;           // 0..31
            unsigned iy  = qy >> 16;

            unsigned adx  = (a512 * dxq + 32768u) >> 16;   // round(a*dx*512)
            unsigned ady  = (a512 * dyq + 32768u) >> 16;
            unsigned adxy = (adx  * dyq + 32768u) >> 16;

            unsigned long long v =
                (unsigned long long)(a512 | (adx << 16)) |
                ((unsigned long long)(ady | (adxy << 16)) << 32);

            atomicAdd(&sh[iy * BXD + ix], v);
        }
    }
    __syncthreads();

    // Flush: widen 16-bit fields to 32-bit, 2 u64 global atomics per bin.
    // Global per-field totals <= ~2e7 << 2^32: no cross-field carry.
    for (int i = threadIdx.x; i < NBINS; i += HIST_THREADS) {
        unsigned long long v = sh[i];
        if (v != 0ull) {
            unsigned long long A = (v & 0xFFFFull) |
                                   (((v >> 16) & 0xFFFFull) << 32);
            unsigned long long B = ((v >> 32) & 0xFFFFull) |
                                   (((v >> 48) & 0xFFFFull) << 32);
            atomicAdd(&gA[i], A);
            atomicAdd(&gB[i], B);
        }
    }
    __threadfence();
    __syncthreads();

    // Last-block-done detection. atomicInc wraps g_ctr back to 0 after the
    // full grid has arrived, keeping state deterministic across replays.
    __shared__ unsigned int is_last;
    if (threadIdx.x == 0) {
        unsigned old = atomicInc(&g_ctr, HIST_BLOCKS - 1);
        is_last = (old == HIST_BLOCKS - 1) ? 1u : 0u;
    }
    __syncthreads();
    if (!is_last) return;

    // ---- finishing block: reconstruct density, compute var(ddof=1) ----
    __shared__ float C00[NBINS], CX[NBINS], CY[NBINS], CXY[NBINS];
    const float inv = 1.0f / 512.0f;
    for (int i = threadIdx.x; i < NBINS; i += HIST_THREADS) {
        // atomicAdd(,0) = coherent L2 read of other blocks' atomic results.
        unsigned long long A = atomicAdd(&gA[i], 0ull);
        unsigned long long B = atomicAdd(&gB[i], 0ull);
        gA[i] = 0ull;                          // reset for next replay
        gB[i] = 0ull;
        float S   = (float)(unsigned)(A & 0xFFFFFFFFull) * inv;
        float Sx  = (float)(unsigned)(A >> 32)           * inv;
        float Sy  = (float)(unsigned)(B & 0xFFFFFFFFull) * inv;
        float Sxy = (float)(unsigned)(B >> 32)           * inv;
        C00[i] = S - Sx - Sy + Sxy;
        CX [i] = Sx - Sxy;
        CY [i] = Sy - Sxy;
        CXY[i] = Sxy;
    }
    __syncthreads();

    float* V = (float*)sh;                     // reuse hist smem for density
    float local_sum = 0.0f;
    for (int b = threadIdx.x; b < NBINS; b += HIST_THREADS) {
        int i = b & 31, j = b >> 5;
        float v = C00[b];
        if (i > 0)          v += CX [b - 1];
        if (j > 0)          v += CY [b - 32];
        if (i > 0 && j > 0) v += CXY[b - 33];
        V[b] = v;
        local_sum += v;
    }

    __shared__ float red[8];
    __shared__ float mean_sh;
    int lane = threadIdx.x & 31;
    int wid  = threadIdx.x >> 5;

    float s = local_sum;
    #pragma unroll
    for (int off = 16; off > 0; off >>= 1)
        s += __shfl_xor_sync(0xFFFFFFFFu, s, off);
    if (lane == 0) red[wid] = s;
    __syncthreads();
    if (threadIdx.x == 0) {
        float t = 0.0f;
        #pragma unroll
        for (int w = 0; w < 8; w++) t += red[w];
        mean_sh = t * (1.0f / (float)NBINS);
    }
    __syncthreads();

    float mean = mean_sh;
    float local_q = 0.0f;
    for (int b = threadIdx.x; b < NBINS; b += HIST_THREADS) {
        float d = V[b] - mean;
        local_q = fmaf(d, d, local_q);
    }
    float q = local_q;
    #pragma unroll
    for (int off = 16; off > 0; off >>= 1)
        q += __shfl_xor_sync(0xFFFFFFFFu, q, off);
    __syncthreads();
    if (lane == 0) red[wid] = q;
    __syncthreads();
    if (threadIdx.x == 0) {
        float t = 0.0f;
        #pragma unroll
        for (int w = 0; w < 8; w++) t += red[w];
        out[0] = t * (1.0f / (float)(NBINS - 1));   // ddof=1
    }
}

extern "C" void kernel_launch(void* const* d_in, const int* in_sizes, int n_in,
                              void* d_out, int out_size) {
    const float* pos  = (const float*)d_in[0];
    const int*   mask = (const int*)d_in[1];      // jax bool -> int32 in harness
    const float* msx  = (const float*)d_in[2];
    const float* msy  = (const float*)d_in[3];

    const float4* x4  = (const float4*)(pos);               // pos[0 : 10M)
    const float4* y4  = (const float4*)(pos + NUM_PHYS);    // pos[11M : 21M), 16B aligned
    const int4*   m4  = (const int4*)(mask);
    const float4* sx4 = (const float4*)(msx);
    const float4* sy4 = (const float4*)(msy);

    fused_kernel<<<HIST_BLOCKS, HIST_THREADS>>>(x4, y4, m4, sx4, sy4,
                                                (float*)d_out);
}

// round 8
// speedup vs baseline: 1.0609x; 1.0609x over previous
#include <cuda_runtime.h>
#include <cstdint>

// Problem constants (match reference)
#define NUM_MOVABLE 10000000
#define NUM_PHYS    11000000
#define BXD 32
#define BYD 32
#define NBINS (BXD * BYD)

#define HIST_BLOCKS 1184   // 8 CTAs/SM on 148 SMs -> 100% occupancy
#define HIST_THREADS 256

// Global scratch accumulators (no cudaMalloc allowed).
// Zero-initialized at module load; the finishing block resets them to zero
// after consuming them, so the "all zero on kernel entry" invariant holds
// across every graph replay. Fixed-point units of 1/512.
// gA = S(low32) | Sx(high32); gB = Sy | Sxy.
__device__ unsigned long long gA[NBINS];
__device__ unsigned long long gB[NBINS];
__device__ unsigned int g_ctr;   // wraps back to 0 every full grid

// Moments at source bin (iy,ix):  S += a, Sx += a*dx, Sy += a*dy, Sxy += a*dx*dy.
// density(j,i) = (S-Sx-Sy+Sxy)[j,i] + (Sx-Sxy)[j,i-1] + (Sy-Sxy)[j-1,i] + Sxy[j-1,i-1].
__global__ void __launch_bounds__(HIST_THREADS, 8)
fused_kernel(const float4* __restrict__ x4,
             const float4* __restrict__ y4,
             const int4*   __restrict__ m4,    // mask is int32 per element
             const float4* __restrict__ sx4,
             const float4* __restrict__ sy4,
             float* __restrict__ out) {
    __shared__ unsigned long long sh[NBINS];   // 4x16-bit fields: S,adx,ady,adxy (1/512 units)
    __shared__ float tail2[2 * NBINS];         // tail only: CY | CXY
    for (int i = threadIdx.x; i < NBINS; i += HIST_THREADS) sh[i] = 0ull;
    __syncthreads();

    const float CLMP  = 30.9999990463f;        // float(31 - 1e-6)
    const float MAGIC = 8388608.0f;            // 2^23, RNE-to-integer trick

    const int n4 = NUM_MOVABLE / 4;            // 2,500,000 exact
    for (int i = blockIdx.x * HIST_THREADS + threadIdx.x; i < n4;
         i += HIST_BLOCKS * HIST_THREADS) {
        float4 x  = __ldg(x4  + i);
        float4 y  = __ldg(y4  + i);
        float4 sx = __ldg(sx4 + i);
        float4 sy = __ldg(sy4 + i);
        int4   m  = __ldg(m4  + i);

        #pragma unroll
        for (int k = 0; k < 4; k++) {
            float xv  = (k == 0) ? x.x  : (k == 1) ? x.y  : (k == 2) ? x.z  : x.w;
            float yv  = (k == 0) ? y.x  : (k == 1) ? y.y  : (k == 2) ? y.z  : y.w;
            float sxv = (k == 0) ? sx.x : (k == 1) ? sx.y : (k == 2) ? sx.z : sx.w;
            float syv = (k == 0) ? sy.x : (k == 1) ? sy.y : (k == 2) ? sy.z : sy.w;
            int   mv  = (k == 0) ? m.x  : (k == 1) ? m.y  : (k == 2) ? m.z  : m.w;

            float fx = fminf(fmaxf(xv * 32.0f, 0.0f), CLMP);
            float fy = fminf(fmaxf(yv * 32.0f, 0.0f), CLMP);
            unsigned qx = __float_as_uint(fmaf(fx, 65536.0f, MAGIC)) & 0x3FFFFF;
            unsigned qy = __float_as_uint(fmaf(fy, 65536.0f, MAGIC)) & 0x3FFFFF;

            float a = fminf(sxv * 32.0f, 1.0f) * fminf(syv * 32.0f, 1.0f);
            if (mv == 0) a = 0.0f;
            unsigned a512 = __float_as_uint(fmaf(a, 512.0f, MAGIC)) & 0xFFFF;

            unsigned dxq = qx & 0xFFFFu;       // dx in 2^-16 units
            unsigned dyq = qy & 0xFFFFu;
            unsigned ix  = qx >> 16;           // 0..31
            unsigned iy  = qy >> 16;

            unsigned adx  = (a512 * dxq + 32768u) >> 16;   // round(a*dx*512)
            unsigned ady  = (a512 * dyq + 32768u) >> 16;
            unsigned adxy = (adx  * dyq + 32768u) >> 16;

            unsigned long long v =
                (unsigned long long)(a512 | (adx << 16)) |
                ((unsigned long long)(ady | (adxy << 16)) << 32);

            atomicAdd(&sh[iy * BXD + ix], v);
        }
    }
    __syncthreads();

    // Flush: widen 16-bit fields to 32-bit, 2 u64 global atomics per bin.
    // Global per-field totals <= ~2e7 << 2^32: no cross-field carry.
    for (int i = threadIdx.x; i < NBINS; i += HIST_THREADS) {
        unsigned long long v = sh[i];
        if (v != 0ull) {
            unsigned long long A = (v & 0xFFFFull) |
                                   (((v >> 16) & 0xFFFFull) << 32);
            unsigned long long B = ((v >> 32) & 0xFFFFull) |
                                   (((v >> 48) & 0xFFFFull) << 32);
            atomicAdd(&gA[i], A);
            atomicAdd(&gB[i], B);
        }
    }
    __threadfence();
    __syncthreads();

    // Last-block-done detection. atomicInc wraps g_ctr back to 0 after the
    // full grid has arrived, keeping state deterministic across replays.
    __shared__ unsigned int is_last;
    if (threadIdx.x == 0) {
        unsigned old = atomicInc(&g_ctr, HIST_BLOCKS - 1);
        is_last = (old == HIST_BLOCKS - 1) ? 1u : 0u;
    }
    __syncthreads();
    if (!is_last) return;

    // ---- finishing block: reconstruct density, compute var(ddof=1) ----
    // Stencil coefficients stored in reused smem:
    //   sf[2b] = C00(b), sf[2b+1] = CX(b)   (overlaying sh)
    //   tail2[b] = CY(b), tail2[NBINS+b] = CXY(b)
    float* sf = (float*)sh;
    const float inv = 1.0f / 512.0f;
    for (int i = threadIdx.x; i < NBINS; i += HIST_THREADS) {
        // atomicAdd(,0) = coherent L2 read of other blocks' atomic results.
        unsigned long long A = atomicAdd(&gA[i], 0ull);
        unsigned long long B = atomicAdd(&gB[i], 0ull);
        gA[i] = 0ull;                          // reset for next replay
        gB[i] = 0ull;
        float S   = (float)(unsigned)(A & 0xFFFFFFFFull) * inv;
        float Sx  = (float)(unsigned)(A >> 32)           * inv;
        float Sy  = (float)(unsigned)(B & 0xFFFFFFFFull) * inv;
        float Sxy = (float)(unsigned)(B >> 32)           * inv;
        sf[2 * i]         = S - Sx - Sy + Sxy;   // C00
        sf[2 * i + 1]     = Sx - Sxy;            // CX
        tail2[i]          = Sy - Sxy;            // CY
        tail2[NBINS + i]  = Sxy;                 // CXY
    }
    __syncthreads();

    // Pass 1: density + sum (keep density in registers, 4 bins/thread)
    float vreg[NBINS / HIST_THREADS];
    float local_sum = 0.0f;
    #pragma unroll
    for (int r = 0; r < NBINS / HIST_THREADS; r++) {
        int b = threadIdx.x + r * HIST_THREADS;
        int i = b & 31, j = b >> 5;
        float v = sf[2 * b];
        if (i > 0)          v += sf[2 * (b - 1) + 1];
        if (j > 0)          v += tail2[b - 32];
        if (i > 0 && j > 0) v += tail2[NBINS + b - 33];
        vreg[r] = v;
        local_sum += v;
    }

    __shared__ float red[8];
    __shared__ float mean_sh;
    int lane = threadIdx.x & 31;
    int wid  = threadIdx.x >> 5;

    float s = local_sum;
    #pragma unroll
    for (int off = 16; off > 0; off >>= 1)
        s += __shfl_xor_sync(0xFFFFFFFFu, s, off);
    if (lane == 0) red[wid] = s;
    __syncthreads();
    if (threadIdx.x == 0) {
        float t = 0.0f;
        #pragma unroll
        for (int w = 0; w < 8; w++) t += red[w];
        mean_sh = t * (1.0f / (float)NBINS);
    }
    __syncthreads();

    // Pass 2: sum of squared deviations
    float mean = mean_sh;
    float local_q = 0.0f;
    #pragma unroll
    for (int r = 0; r < NBINS / HIST_THREADS; r++) {
        float d = vreg[r] - mean;
        local_q = fmaf(d, d, local_q);
    }
    float q = local_q;
    #pragma unroll
    for (int off = 16; off > 0; off >>= 1)
        q += __shfl_xor_sync(0xFFFFFFFFu, q, off);
    __syncthreads();
    if (lane == 0) red[wid] = q;
    __syncthreads();
    if (threadIdx.x == 0) {
        float t = 0.0f;
        #pragma unroll
        for (int w = 0; w < 8; w++) t += red[w];
        out[0] = t * (1.0f / (float)(NBINS - 1));   // ddof=1
    }
}

extern "C" void kernel_launch(void* const* d_in, const int* in_sizes, int n_in,
                              void* d_out, int out_size) {
    const float* pos  = (const float*)d_in[0];
    const int*   mask = (const int*)d_in[1];      // jax bool -> int32 in harness
    const float* msx  = (const float*)d_in[2];
    const float* msy  = (const float*)d_in[3];

    const float4* x4  = (const float4*)(pos);               // pos[0 : 10M)
    const float4* y4  = (const float4*)(pos + NUM_PHYS);    // pos[11M : 21M), 16B aligned
    const int4*   m4  = (const int4*)(mask);
    const float4* sx4 = (const float4*)(msx);
    const float4* sy4 = (const float4*)(msy);

    fused_kernel<<<HIST_BLOCKS, HIST_THREADS>>>(x4, y4, m4, sx4, sy4,
                                                (float*)d_out);
}